// round 12
// baseline (speedup 1.0000x reference)
#include <cuda_runtime.h>
#include <cuda_bf16.h>
#include <cstdint>

// DrugBAN fused kernel, R11: R3 balanced grid + R10 evict_last cache policy.
//
// Algebra (verified, rel_err ~2e-7): softmax rows sum to 1, so
//   drug_ctx[b,:] = (1/NT) * segment_sum(drug_x)  (rank < NMAX only)
//   tgt_ctx[b,:]  = mean_t target_h[b,t,:]
// W_a / GEMM / softmax cancel.
//
// R10 win: createpolicy evict_last on the champion access shape -> 13.0us
// (replay L2 warmth; ncu cold profile unchanged). R11 composes that with
// R3's balanced 64x16 grid (t-split target blocks, deterministic ticket
// combine), which was cold-neutral but removes the heavy-block tail that
// now dominates the warm runtime.
//
// Inputs: d_in[0] drug_x f32[16384,256], d_in[1] batch_idx i32[16384] sorted,
//         d_in[2] target_h f32[64,1024,256], d_in[3] W_a (unused).
// Output: f32 [64, 512] = [drug_ctx | tgt_ctx].

#define NT_LEN   1024
#define NMAX_CAP 512
#define BATCH_B  64
#define TCHUNKS  3

__device__ float g_partial[BATCH_B * 4 * TCHUNKS * 64];
__device__ int   g_ticket[BATCH_B * 4];   // zero-init; self-resetting

__device__ __forceinline__ uint64_t mk_policy() {
    uint64_t pol;
    asm("createpolicy.fractional.L2::evict_last.b64 %0, 1.0;" : "=l"(pol));
    return pol;
}

__device__ __forceinline__ float4 ldg_pol(const float4* p, uint64_t pol) {
    float4 v;
    asm("ld.global.nc.L2::cache_hint.v4.f32 {%0,%1,%2,%3}, [%4], %5;"
        : "=f"(v.x), "=f"(v.y), "=f"(v.z), "=f"(v.w)
        : "l"(p), "l"(pol));
    return v;
}

__device__ __forceinline__ int lb_search(const int* __restrict__ a, int n, int key) {
    int lo = 0, hi = n;
    while (lo < hi) {
        int mid = (lo + hi) >> 1;
        if (__ldg(a + mid) < key) lo = mid + 1; else hi = mid;
    }
    return lo;
}

__device__ __forceinline__ void f4_add(float4& d, const float4 s) {
    d.x += s.x; d.y += s.y; d.z += s.z; d.w += s.w;
}

__device__ __forceinline__ void block_reduce_16(float4* red, int tid) {
    __syncthreads();
    #pragma unroll
    for (int s = 128; s >= 16; s >>= 1) {
        if (tid < s) f4_add(red[tid], red[tid + s]);
        __syncthreads();
    }
}

__global__ __launch_bounds__(256, 8)
void drugban_fused_kernel(const float* __restrict__ drug_x,
                          const int*   __restrict__ batch_idx,
                          const float* __restrict__ target_h,
                          float*       __restrict__ out,
                          int n_nodes) {
    const int b    = blockIdx.x;     // batch 0..63
    const int part = blockIdx.y;     // 0..3 drug quarters, 4..15 target (q,c)
    const int tid  = threadIdx.x;    // 256 threads
    const int col  = tid & 15;       // float4 column within the 64-dim slice
    const int rg   = tid >> 4;       // 0..15 row group

    __shared__ float4 red[256];
    __shared__ int s_ticket;

    const uint64_t pol = mk_policy();
    const float scale = 1.0f / (float)NT_LEN;
    float4 acc = make_float4(0.f, 0.f, 0.f, 0.f);

    if (part < 4) {
        // ---- drug segment sum, dims [part*64, +64) ----
        int start = lb_search(batch_idx, n_nodes, b);
        int end   = lb_search(batch_idx, n_nodes, b + 1);
        if (end - start > NMAX_CAP) end = start + NMAX_CAP;

        const float4* base = reinterpret_cast<const float4*>(drug_x)
                             + (size_t)part * 16 + col;   // row = 64 float4
        int i = start + rg;
        for (; i + 16 < end; i += 32) {
            float4 v0 = ldg_pol(base + (size_t)i * 64, pol);
            float4 v1 = ldg_pol(base + (size_t)(i + 16) * 64, pol);
            acc.x += v0.x + v1.x; acc.y += v0.y + v1.y;
            acc.z += v0.z + v1.z; acc.w += v0.w + v1.w;
        }
        if (i < end) f4_add(acc, ldg_pol(base + (size_t)i * 64, pol));

        red[tid] = acc;
        block_reduce_16(red, tid);

        if (tid < 16) {
            float4 r = red[tid];
            r.x *= scale; r.y *= scale; r.z *= scale; r.w *= scale;
            reinterpret_cast<float4*>(out + b * 512 + part * 64)[tid] = r;
        }
    } else {
        // ---- target partial sum: quarter q, t-chunk c ----
        const int idx = part - 4;
        const int q = idx & 3;
        const int c = idx >> 2;
        const int t0 = (c * NT_LEN) / TCHUNKS;
        const int t1 = ((c + 1) * NT_LEN) / TCHUNKS;

        const float4* base = reinterpret_cast<const float4*>(target_h)
                             + (size_t)b * (NT_LEN * 64) + (size_t)q * 16 + col;
        #pragma unroll 4
        for (int t = t0 + rg; t < t1; t += 16)
            f4_add(acc, ldg_pol(base + (size_t)t * 64, pol));

        red[tid] = acc;
        block_reduce_16(red, tid);

        // write partial (unscaled) to scratch
        if (tid < 16)
            reinterpret_cast<float4*>(
                g_partial + (((b * 4 + q) * TCHUNKS + c) * 64))[tid] = red[tid];

        __threadfence();
        __syncthreads();
        if (tid == 0) s_ticket = atomicAdd(&g_ticket[b * 4 + q], 1);
        __syncthreads();

        if (s_ticket == TCHUNKS - 1) {
            __threadfence();  // acquire peers' partials
            if (tid < 16) {
                const float4* pbase = reinterpret_cast<const float4*>(
                    g_partial + ((b * 4 + q) * TCHUNKS * 64));
                // fixed order c = 0,1,2 -> deterministic
                float4 r  = pbase[tid];
                float4 p1 = pbase[16 + tid];
                float4 p2 = pbase[32 + tid];
                r.x = (r.x + p1.x + p2.x) * scale;
                r.y = (r.y + p1.y + p2.y) * scale;
                r.z = (r.z + p1.z + p2.z) * scale;
                r.w = (r.w + p1.w + p2.w) * scale;
                reinterpret_cast<float4*>(out + b * 512 + 256 + q * 64)[tid] = r;
            }
            if (tid == 0) g_ticket[b * 4 + q] = 0;  // reset for next replay
        }
    }
}

extern "C" void kernel_launch(void* const* d_in, const int* in_sizes, int n_in,
                              void* d_out, int out_size) {
    const float* drug_x    = (const float*)d_in[0];
    const int*   batch_idx = (const int*)d_in[1];
    const float* target_h  = (const float*)d_in[2];
    // d_in[3] (W_a) cancels out mathematically; unused.
    float* out = (float*)d_out;
    int n_nodes = in_sizes[1];

    dim3 grid(BATCH_B, 4 + 4 * TCHUNKS);   // 64 x 16 = 1024 uniform blocks
    drugban_fused_kernel<<<grid, 256>>>(drug_x, batch_idx, target_h, out, n_nodes);
}